// round 1
// baseline (speedup 1.0000x reference)
#include <cuda_runtime.h>

#define BB  4
#define CIN 320
#define G   32
#define CPG 10
#define DD  48
#define HH  72
#define WW  240
#define HW  (HH*WW)          // 17280
#define DHW (DD*HW)          // 829440
#define VOL_ELEMS (BB*G*DHW) // 106,168,320

// Scratch (allocation-free: device globals)
__device__ float g_vol   [VOL_ELEMS];   // [B][G=ic][D][H][W]  gwc cost volume
__device__ float g_vol2  [VOL_ELEMS];   // [B][32oc][D][H][W]  conv1+BN+ReLU
__device__ float g_logits[BB*DHW];      // [B][D][H][W]

// ---------------------------------------------------------------------------
// Kernel 1: groupwise-correlation cost volume.
// One block per (b, h, g). Load the 10-channel group rows of fl/fr into smem,
// then compute all 48 disparities x 240 widths.
// vol[b,g,d,h,w] = (w>=d) ? mean_c fl[c,h,w]*fr[c,h,w-d] : 0
// ---------------------------------------------------------------------------
__global__ void __launch_bounds__(256) vol_kernel(const float* __restrict__ fl,
                                                  const float* __restrict__ fr) {
    __shared__ float sFl[CPG][WW];
    __shared__ float sFr[CPG][WW];
    const int h = blockIdx.x, g = blockIdx.y, b = blockIdx.z;
    const int tid = threadIdx.x;

    const float* flb = fl + ((size_t)b*CIN + g*CPG)*HW + h*WW;
    const float* frb = fr + ((size_t)b*CIN + g*CPG)*HW + h*WW;
    for (int i = tid; i < CPG*WW; i += 256) {
        int c = i / WW, w = i % WW;
        sFl[c][w] = flb[c*HW + w];
        sFr[c][w] = frb[c*HW + w];
    }
    __syncthreads();

    float* dst = g_vol + ((size_t)b*G + g)*DHW + h*WW;
    for (int i = tid; i < DD*WW; i += 256) {
        int d = i / WW, w = i % WW;
        float v = 0.f;
        if (w >= d) {
            float s = 0.f;
            #pragma unroll
            for (int c = 0; c < CPG; c++) s += sFl[c][w] * sFr[c][w-d];
            v = s * (1.0f/CPG);
        }
        dst[d*HW + w] = v;
    }
}

// ---------------------------------------------------------------------------
// Kernel 2: Conv3d(32->32, k=3, pad=1) + BatchNorm(eval) + ReLU, fused.
// One block per (b, d, h): computes all 32 oc x 240 w outputs of that row.
// smem: all weights repacked [r=ic*27+k][33 pad][oc] + one (kd,kh) slab
// [32ic][244] (w = -1..240, zero padded). Thread tile: 2 oc x 15 w.
// ---------------------------------------------------------------------------
#define SW_STRIDE 33
#define CONV1_SMEM ((864*SW_STRIDE + 32*244) * sizeof(float))

__global__ void __launch_bounds__(256) conv1_kernel(
        const float* __restrict__ w1, const float* __restrict__ gamma,
        const float* __restrict__ beta, const float* __restrict__ mean,
        const float* __restrict__ var) {
    extern __shared__ float sm[];
    float* sW  = sm;               // [864][33] : sW[r*33+oc] = w1[oc*864+r]
    float* sIn = sm + 864*SW_STRIDE; // [32][244]

    const int h = blockIdx.x, d = blockIdx.y, b = blockIdx.z;
    const int tid = threadIdx.x;

    // Stage weights: coalesced global read, conflict-free smem (pad 33).
    for (int i = tid; i < 32*864; i += 256) {
        int oc = i / 864, r = i % 864;
        sW[r*SW_STRIDE + oc] = w1[i];
    }

    const int ocg = tid & 15;      // 16 groups of 2 oc
    const int wg  = tid >> 4;      // 16 groups of 15 w
    const int oc0 = ocg * 2;
    const int w0  = wg * 15;

    float acc[2][15];
    #pragma unroll
    for (int j = 0; j < 15; j++) { acc[0][j] = 0.f; acc[1][j] = 0.f; }

    for (int kd = 0; kd < 3; kd++) {
        const int dd = d + kd - 1;
        if (dd < 0 || dd >= DD) continue;          // block-uniform
        for (int kh = 0; kh < 3; kh++) {
            const int hhr = h + kh - 1;
            if (hhr < 0 || hhr >= HH) continue;    // block-uniform
            __syncthreads();
            const float* src = g_vol + (size_t)b*G*DHW + (size_t)dd*HW + hhr*WW;
            for (int i = tid; i < 32*242; i += 256) {
                int ic = i / 242, j = i % 242;
                int w = j - 1;
                sIn[ic*244 + j] = (w >= 0 && w < WW) ? src[ic*DHW + w] : 0.f;
            }
            __syncthreads();
            const int kbase = kd*9 + kh*3;
            for (int ic = 0; ic < 32; ic++) {
                float x[17];
                #pragma unroll
                for (int j = 0; j < 17; j++) x[j] = sIn[ic*244 + w0 + j];
                #pragma unroll
                for (int kw = 0; kw < 3; kw++) {
                    const float wa = sW[(ic*27 + kbase + kw)*SW_STRIDE + oc0];
                    const float wb = sW[(ic*27 + kbase + kw)*SW_STRIDE + oc0 + 1];
                    #pragma unroll
                    for (int j = 0; j < 15; j++) {
                        acc[0][j] = fmaf(wa, x[j+kw], acc[0][j]);
                        acc[1][j] = fmaf(wb, x[j+kw], acc[1][j]);
                    }
                }
            }
        }
    }

    // Fused BN (eval) + ReLU epilogue
    #pragma unroll
    for (int p = 0; p < 2; p++) {
        const int oc = oc0 + p;
        const float sc = gamma[oc] * rsqrtf(var[oc] + 1e-5f);
        const float sh = beta[oc] - mean[oc] * sc;
        float* dst = g_vol2 + ((size_t)b*G + oc)*DHW + (size_t)d*HW + h*WW + w0;
        #pragma unroll
        for (int j = 0; j < 15; j++) {
            float v = fmaf(acc[p][j], sc, sh);
            dst[j] = v > 0.f ? v : 0.f;
        }
    }
}

// ---------------------------------------------------------------------------
// Kernel 3: Conv3d(32->1, k=3, pad=1) -> logits [B][D][H][W]
// One block per (b, d, h); one thread per w.
// ---------------------------------------------------------------------------
__global__ void __launch_bounds__(256) conv2_kernel(const float* __restrict__ w2) {
    __shared__ float sW2[864];       // [ic*27 + k]
    __shared__ float sIn[32*244];

    const int h = blockIdx.x, d = blockIdx.y, b = blockIdx.z;
    const int tid = threadIdx.x;
    const int w = tid;

    for (int i = tid; i < 864; i += 256) sW2[i] = w2[i];

    float accv = 0.f;
    for (int kd = 0; kd < 3; kd++) {
        const int dd = d + kd - 1;
        if (dd < 0 || dd >= DD) continue;
        for (int kh = 0; kh < 3; kh++) {
            const int hhr = h + kh - 1;
            if (hhr < 0 || hhr >= HH) continue;
            __syncthreads();
            const float* src = g_vol2 + (size_t)b*G*DHW + (size_t)dd*HW + hhr*WW;
            for (int i = tid; i < 32*242; i += 256) {
                int ic = i / 242, j = i % 242;
                int ww = j - 1;
                sIn[ic*244 + j] = (ww >= 0 && ww < WW) ? src[ic*DHW + ww] : 0.f;
            }
            __syncthreads();
            const int kbase = kd*9 + kh*3;
            if (w < WW) {
                #pragma unroll 4
                for (int ic = 0; ic < 32; ic++) {
                    const float x0 = sIn[ic*244 + w    ];
                    const float x1 = sIn[ic*244 + w + 1];
                    const float x2 = sIn[ic*244 + w + 2];
                    accv = fmaf(sW2[ic*27 + kbase    ], x0, accv);
                    accv = fmaf(sW2[ic*27 + kbase + 1], x1, accv);
                    accv = fmaf(sW2[ic*27 + kbase + 2], x2, accv);
                }
            }
        }
    }
    if (w < WW)
        g_logits[((size_t)b*DD + d)*HW + h*WW + w] = accv;
}

// ---------------------------------------------------------------------------
// Kernel 4: softmax over D + disparity expectation -> out [B][H][W]
// ---------------------------------------------------------------------------
__global__ void __launch_bounds__(256) softmax_kernel(float* __restrict__ out) {
    const int h = blockIdx.x, b = blockIdx.y;
    const int w = threadIdx.x;
    if (w >= WW) return;
    const float* p = g_logits + (size_t)b*DHW + h*WW + w;
    float m = -1e30f;
    #pragma unroll 4
    for (int d = 0; d < DD; d++) m = fmaxf(m, p[d*HW]);
    float s = 0.f, e = 0.f;
    #pragma unroll 4
    for (int d = 0; d < DD; d++) {
        float t = __expf(p[d*HW] - m);
        s += t;
        e += t * (float)d;
    }
    out[(size_t)b*HW + h*WW + w] = e / s;
}

// ---------------------------------------------------------------------------
extern "C" void kernel_launch(void* const* d_in, const int* in_sizes, int n_in,
                              void* d_out, int out_size) {
    const float* fl    = (const float*)d_in[0];
    const float* fr    = (const float*)d_in[1];
    const float* w1    = (const float*)d_in[2];
    const float* gamma = (const float*)d_in[3];
    const float* beta  = (const float*)d_in[4];
    const float* mean  = (const float*)d_in[5];
    const float* var   = (const float*)d_in[6];
    const float* w2    = (const float*)d_in[7];
    float* out = (float*)d_out;

    cudaFuncSetAttribute(conv1_kernel,
                         cudaFuncAttributeMaxDynamicSharedMemorySize,
                         (int)CONV1_SMEM);

    vol_kernel   <<<dim3(HH, G,  BB), 256>>>(fl, fr);
    conv1_kernel <<<dim3(HH, DD, BB), 256, CONV1_SMEM>>>(w1, gamma, beta, mean, var);
    conv2_kernel <<<dim3(HH, DD, BB), 256>>>(w2);
    softmax_kernel<<<dim3(HH, BB), 256>>>(out);
}

// round 2
// speedup vs baseline: 1.4533x; 1.4533x over previous
#include <cuda_runtime.h>
#include <cstdint>

#define BB  4
#define CIN 320
#define G   32
#define CPG 10
#define DD  48
#define HH  72
#define WW  240
#define HW  (HH*WW)          // 17280
#define DHW (DD*HW)          // 829440
#define VOL_ELEMS (BB*G*DHW) // 106,168,320

// Scratch (allocation-free: device globals)
__device__ float g_vol   [VOL_ELEMS];   // [B][G=ic][D][H][W]  gwc cost volume
__device__ float g_vol2  [VOL_ELEMS];   // [B][32oc][D][H][W]  conv1+BN+ReLU
__device__ float g_logits[BB*DHW];      // [B][D][H][W]

// ---------------------------------------------------------------------------
// Packed f32x2 helpers (Blackwell: FFMA2 only reachable via PTX fma.rn.f32x2)
// ---------------------------------------------------------------------------
__device__ __forceinline__ uint64_t pack2(float lo, float hi) {
    uint64_t r;
    asm("mov.b64 %0, {%1, %2};" : "=l"(r) : "f"(lo), "f"(hi));
    return r;
}
__device__ __forceinline__ uint64_t fma2(uint64_t a, uint64_t b, uint64_t c) {
    uint64_t d;
    asm("fma.rn.f32x2 %0, %1, %2, %3;" : "=l"(d) : "l"(a), "l"(b), "l"(c));
    return d;
}
__device__ __forceinline__ void unpack2(uint64_t v, float& lo, float& hi) {
    asm("mov.b64 {%0, %1}, %2;" : "=f"(lo), "=f"(hi) : "l"(v));
}

// ---------------------------------------------------------------------------
// Kernel 1: groupwise-correlation cost volume.
// One block per (b, h, g). vol[b,g,d,h,w] = (w>=d) ? mean_c fl[w]*fr[w-d] : 0
// ---------------------------------------------------------------------------
__global__ void __launch_bounds__(256) vol_kernel(const float* __restrict__ fl,
                                                  const float* __restrict__ fr) {
    __shared__ float sFl[CPG][WW];
    __shared__ float sFr[CPG][WW];
    const int h = blockIdx.x, g = blockIdx.y, b = blockIdx.z;
    const int tid = threadIdx.x;

    const float* flb = fl + ((size_t)b*CIN + g*CPG)*HW + h*WW;
    const float* frb = fr + ((size_t)b*CIN + g*CPG)*HW + h*WW;
    for (int i = tid; i < CPG*WW; i += 256) {
        int c = i / WW, w = i % WW;
        sFl[c][w] = flb[c*HW + w];
        sFr[c][w] = frb[c*HW + w];
    }
    __syncthreads();

    float* dst = g_vol + ((size_t)b*G + g)*DHW + h*WW;
    for (int i = tid; i < DD*WW; i += 256) {
        int d = i / WW, w = i % WW;
        float v = 0.f;
        if (w >= d) {
            float s = 0.f;
            #pragma unroll
            for (int c = 0; c < CPG; c++) s += sFl[c][w] * sFr[c][w-d];
            v = s * (1.0f/CPG);
        }
        dst[d*HW + w] = v;
    }
}

// ---------------------------------------------------------------------------
// Kernel 2: Conv3d(32->32, k=3, pad=1) + BN(eval) + ReLU, fused.
// 512-thread block handles TWO h rows of one (b, d): halves of the block each
// own one h row + one input slab buffer. Weights staged once per block into
// smem packed so each thread's 2 output channels load as one LDS.64.
// Thread tile: 2 oc (packed f32x2) x 15 w. All MMA math is fma.rn.f32x2.
// ---------------------------------------------------------------------------
#define WSTRIDE 34          // 34 floats: keeps oc0-even pairs 8B aligned, few conflicts
#define SLAB    244
#define CONV1_SMEM ((864*WSTRIDE + 2*32*SLAB) * sizeof(float))   // ~176 KB

__global__ void __launch_bounds__(512) conv1_kernel(
        const float* __restrict__ w1, const float* __restrict__ gamma,
        const float* __restrict__ beta, const float* __restrict__ mean,
        const float* __restrict__ var) {
    extern __shared__ float sm[];
    float* sW  = sm;                    // [864][WSTRIDE] : sW[r*WS + oc] = w1[oc*864+r]
    float* sIn = sm + 864*WSTRIDE;      // [2][32][SLAB]

    const int tid  = threadIdx.x;
    const int half = tid >> 8;          // which h row
    const int t    = tid & 255;
    const int hb = blockIdx.x, d = blockIdx.y, b = blockIdx.z;
    const int h  = hb*2 + half;

    // Stage all weights (coalesced GMEM; 2-way STS conflicts only, one-time)
    for (int i = tid; i < 32*864; i += 512) {
        int oc = i / 864, r = i % 864;
        sW[r*WSTRIDE + oc] = w1[i];
    }

    const int oc0 = (t & 15) * 2;       // even -> packed pair aligned
    const int w0  = (t >> 4) * 15;
    float* sInH = sIn + half*(32*SLAB);

    uint64_t acc[15];
    #pragma unroll
    for (int j = 0; j < 15; j++) acc[j] = 0ull;

    for (int kd = 0; kd < 3; kd++) {
        const int dd = d + kd - 1;
        if (dd < 0 || dd >= DD) continue;                 // block-uniform
        const float* srcb = g_vol + (size_t)b*G*DHW + (size_t)dd*HW;
        for (int kh = 0; kh < 3; kh++) {
            const int hhr = h + kh - 1;
            const bool hv = (hhr >= 0 && hhr < HH);       // differs per half: zero-fill
            const float* src = srcb + (hv ? hhr : 0)*WW;
            __syncthreads();
            for (int i = t; i < 32*242; i += 256) {
                int ic = i / 242, j = i % 242;
                int w = j - 1;
                float v = 0.f;
                if (hv && w >= 0 && w < WW) v = src[ic*DHW + w];
                sInH[ic*SLAB + j] = v;
            }
            __syncthreads();
            const int kbase = kd*9 + kh*3;
            for (int ic = 0; ic < 32; ic++) {
                uint64_t xp[17];
                #pragma unroll
                for (int j = 0; j < 17; j++) {
                    float xv = sInH[ic*SLAB + w0 + j];
                    xp[j] = pack2(xv, xv);
                }
                const float* wrow = &sW[(ic*27 + kbase)*WSTRIDE + oc0];
                #pragma unroll
                for (int kw = 0; kw < 3; kw++) {
                    uint64_t wp = *reinterpret_cast<const uint64_t*>(wrow + kw*WSTRIDE);
                    #pragma unroll
                    for (int j = 0; j < 15; j++)
                        acc[j] = fma2(wp, xp[j+kw], acc[j]);
                }
            }
        }
    }

    // Fused BN (eval) + ReLU epilogue
    const float sc0 = gamma[oc0]   * rsqrtf(var[oc0]   + 1e-5f);
    const float sc1 = gamma[oc0+1] * rsqrtf(var[oc0+1] + 1e-5f);
    const float sh0 = beta[oc0]   - mean[oc0]   * sc0;
    const float sh1 = beta[oc0+1] - mean[oc0+1] * sc1;
    float* dst0 = g_vol2 + ((size_t)b*G + oc0)*DHW + (size_t)d*HW + h*WW + w0;
    float* dst1 = dst0 + DHW;
    #pragma unroll
    for (int j = 0; j < 15; j++) {
        float a, c;
        unpack2(acc[j], a, c);
        float v0 = fmaf(a, sc0, sh0);
        float v1 = fmaf(c, sc1, sh1);
        dst0[j] = v0 > 0.f ? v0 : 0.f;
        dst1[j] = v1 > 0.f ? v1 : 0.f;
    }
}

// ---------------------------------------------------------------------------
// Kernel 3: Conv3d(32->1, k=3, pad=1) -> logits [B][D][H][W]
// One block per (b, d, h); one thread per w. 3 accumulators break the chain.
// ---------------------------------------------------------------------------
__global__ void __launch_bounds__(256) conv2_kernel(const float* __restrict__ w2) {
    __shared__ float sW2[864];
    __shared__ float sIn[32*SLAB];

    const int h = blockIdx.x, d = blockIdx.y, b = blockIdx.z;
    const int tid = threadIdx.x;
    const int w = tid;

    for (int i = tid; i < 864; i += 256) sW2[i] = w2[i];

    float a0 = 0.f, a1 = 0.f, a2 = 0.f;
    for (int kd = 0; kd < 3; kd++) {
        const int dd = d + kd - 1;
        if (dd < 0 || dd >= DD) continue;
        for (int kh = 0; kh < 3; kh++) {
            const int hhr = h + kh - 1;
            if (hhr < 0 || hhr >= HH) continue;
            __syncthreads();
            const float* src = g_vol2 + (size_t)b*G*DHW + (size_t)dd*HW + hhr*WW;
            for (int i = tid; i < 32*242; i += 256) {
                int ic = i / 242, j = i % 242;
                int ww = j - 1;
                sIn[ic*SLAB + j] = (ww >= 0 && ww < WW) ? src[ic*DHW + ww] : 0.f;
            }
            __syncthreads();
            const int kbase = kd*9 + kh*3;
            if (w < WW) {
                #pragma unroll 8
                for (int ic = 0; ic < 32; ic++) {
                    a0 = fmaf(sW2[ic*27 + kbase    ], sIn[ic*SLAB + w    ], a0);
                    a1 = fmaf(sW2[ic*27 + kbase + 1], sIn[ic*SLAB + w + 1], a1);
                    a2 = fmaf(sW2[ic*27 + kbase + 2], sIn[ic*SLAB + w + 2], a2);
                }
            }
        }
    }
    if (w < WW)
        g_logits[((size_t)b*DD + d)*HW + h*WW + w] = a0 + a1 + a2;
}

// ---------------------------------------------------------------------------
// Kernel 4: softmax over D + disparity expectation -> out [B][H][W]
// ---------------------------------------------------------------------------
__global__ void __launch_bounds__(256) softmax_kernel(float* __restrict__ out) {
    const int h = blockIdx.x, b = blockIdx.y;
    const int w = threadIdx.x;
    if (w >= WW) return;
    const float* p = g_logits + (size_t)b*DHW + h*WW + w;
    float m = -1e30f;
    #pragma unroll 4
    for (int d = 0; d < DD; d++) m = fmaxf(m, p[d*HW]);
    float s = 0.f, e = 0.f;
    #pragma unroll 4
    for (int d = 0; d < DD; d++) {
        float t = __expf(p[d*HW] - m);
        s += t;
        e += t * (float)d;
    }
    out[(size_t)b*HW + h*WW + w] = e / s;
}

// ---------------------------------------------------------------------------
extern "C" void kernel_launch(void* const* d_in, const int* in_sizes, int n_in,
                              void* d_out, int out_size) {
    const float* fl    = (const float*)d_in[0];
    const float* fr    = (const float*)d_in[1];
    const float* w1    = (const float*)d_in[2];
    const float* gamma = (const float*)d_in[3];
    const float* beta  = (const float*)d_in[4];
    const float* mean  = (const float*)d_in[5];
    const float* var   = (const float*)d_in[6];
    const float* w2    = (const float*)d_in[7];
    float* out = (float*)d_out;

    cudaFuncSetAttribute(conv1_kernel,
                         cudaFuncAttributeMaxDynamicSharedMemorySize,
                         (int)CONV1_SMEM);

    vol_kernel    <<<dim3(HH, G,  BB), 256>>>(fl, fr);
    conv1_kernel  <<<dim3(HH/2, DD, BB), 512, CONV1_SMEM>>>(w1, gamma, beta, mean, var);
    conv2_kernel  <<<dim3(HH, DD, BB), 256>>>(w2);
    softmax_kernel<<<dim3(HH, BB), 256>>>(out);
}

// round 6
// speedup vs baseline: 2.0062x; 1.3804x over previous
#include <cuda_runtime.h>
#include <cuda_bf16.h>
#include <cstdint>

#define BB  4
#define CIN 320
#define G   32
#define CPG 10
#define DD  48
#define HH  72
#define WW  240
#define HW  (HH*WW)          // 17280
#define DHW (DD*HW)          // 829440
#define VOL_ELEMS (BB*G*DHW) // 106,168,320

// Scratch (allocation-free: device globals)
__device__ float g_vol   [VOL_ELEMS];   // [B][G=ic][D][H][W]  gwc cost volume
__device__ float g_vol2  [VOL_ELEMS];   // [B][32oc][D][H][W]  conv1+BN+ReLU
__device__ float g_logits[BB*DHW];      // [B][D][H][W]

// ===========================================================================
// sm_80-ISA tensor-core helpers (valid on baseline sm_100 target)
// ===========================================================================
__device__ __forceinline__ uint32_t smem_to_u32(const void* p) {
    uint32_t a;
    asm("{ .reg .u64 t; cvta.to.shared.u64 t, %1; cvt.u32.u64 %0, t; }"
        : "=r"(a) : "l"(p));
    return a;
}
__device__ __forceinline__ void ldsm_x4(uint32_t* r, uint32_t addr) {
    asm volatile("ldmatrix.sync.aligned.m8n8.x4.shared.b16 {%0,%1,%2,%3}, [%4];"
        : "=r"(r[0]), "=r"(r[1]), "=r"(r[2]), "=r"(r[3]) : "r"(addr));
}
__device__ __forceinline__ void ldsm_x4_t(uint32_t* r, uint32_t addr) {
    asm volatile("ldmatrix.sync.aligned.m8n8.x4.trans.shared.b16 {%0,%1,%2,%3}, [%4];"
        : "=r"(r[0]), "=r"(r[1]), "=r"(r[2]), "=r"(r[3]) : "r"(addr));
}
__device__ __forceinline__ void mma_bf16(float* d, const uint32_t* a,
                                         uint32_t b0, uint32_t b1) {
    asm volatile(
        "mma.sync.aligned.m16n8k16.row.col.f32.bf16.bf16.f32 "
        "{%0,%1,%2,%3}, {%4,%5,%6,%7}, {%8,%9}, {%0,%1,%2,%3};"
        : "+f"(d[0]), "+f"(d[1]), "+f"(d[2]), "+f"(d[3])
        : "r"(a[0]), "r"(a[1]), "r"(a[2]), "r"(a[3]), "r"(b0), "r"(b1));
}

// ---------------------------------------------------------------------------
// Kernel 1: groupwise-correlation cost volume (unchanged, known-good)
// ---------------------------------------------------------------------------
__global__ void __launch_bounds__(256) vol_kernel(const float* __restrict__ fl,
                                                  const float* __restrict__ fr) {
    __shared__ float sFl[CPG][WW];
    __shared__ float sFr[CPG][WW];
    const int h = blockIdx.x, g = blockIdx.y, b = blockIdx.z;
    const int tid = threadIdx.x;

    const float* flb = fl + ((size_t)b*CIN + g*CPG)*HW + h*WW;
    const float* frb = fr + ((size_t)b*CIN + g*CPG)*HW + h*WW;
    for (int i = tid; i < CPG*WW; i += 256) {
        int c = i / WW, w = i % WW;
        sFl[c][w] = flb[c*HW + w];
        sFr[c][w] = frb[c*HW + w];
    }
    __syncthreads();

    float* dst = g_vol + ((size_t)b*G + g)*DHW + h*WW;
    for (int i = tid; i < DD*WW; i += 256) {
        int d = i / WW, w = i % WW;
        float v = 0.f;
        if (w >= d) {
            float s = 0.f;
            #pragma unroll
            for (int c = 0; c < CPG; c++) s += sFl[c][w] * sFr[c][w-d];
            v = s * (1.0f/CPG);
        }
        dst[d*HW + w] = v;
    }
}

// ---------------------------------------------------------------------------
// Kernel 2: Conv3d(32->32,k3,p1)+BN+ReLU via mma.sync bf16, 3-pass hi/lo.
// One block (512 thr = 16 warps) per (b,d,h) output row.
//   A slab (per kd,kh stage): rows r=0..263 hold x[r-1] over ic (bf16,
//     stride 40 elems = 80B -> conflict-free ldmatrix), hi + lo buffers.
//   B (per stage): [hi/lo][kw][ic][oc] bf16, stride 40.
//   Warp w owns M-tile rows 16w..16w+15 = output w positions; kw taps fold
//   into ONE accumulator via A-tile row shift (+kw). K = 32 ic = 2 k-steps.
//   D[m] = sum_kw sum_ic B_kw[ic]*x[m+kw-1]  -> BN+ReLU -> store (m<240).
// ---------------------------------------------------------------------------
#define ASTRIDE 40
#define AROWS   264
#define SA_H    0
#define SA_L    (AROWS*ASTRIDE*2)            // 21120
#define SB_OFF  (2*AROWS*ASTRIDE*2)          // 42240
#define SB_SIZE (2*3*32*ASTRIDE*2)           // 15360
#define SBN_OFF (SB_OFF + SB_SIZE)           // 57600
#define CONV1_SMEM (SBN_OFF + 256)           // 57856

__global__ void __launch_bounds__(512)
conv1_mma_kernel(const float* __restrict__ w1, const float* __restrict__ gamma,
                 const float* __restrict__ beta, const float* __restrict__ mean,
                 const float* __restrict__ var) {
    extern __shared__ char smc[];
    const uint32_t sb = smem_to_u32(smc);
    float* sBN = (float*)(smc + SBN_OFF);    // sc[32], sh[32]

    const int tid = threadIdx.x, wid = tid >> 5, t = tid & 31;
    const int h = blockIdx.x, d = blockIdx.y, b = blockIdx.z;
    const int m0 = wid * 16;
    const uint32_t lrow = (uint32_t)(t & 15);
    const uint32_t lcol = (uint32_t)((t & 16) >> 1);   // 0 or 8

    if (tid < 32) {
        float sc = gamma[tid] * rsqrtf(var[tid] + 1e-5f);
        sBN[tid] = sc;
        sBN[32 + tid] = beta[tid] - mean[tid] * sc;
    }

    float acc[4][4];                          // 4 n-tiles x 4 regs
    #pragma unroll
    for (int n = 0; n < 4; n++)
        #pragma unroll
        for (int j = 0; j < 4; j++) acc[n][j] = 0.f;

    const float* volb = g_vol + (size_t)b*G*DHW;

    for (int kd = 0; kd < 3; kd++) {
        const int dd = d + kd - 1;
        if (dd < 0 || dd >= DD) continue;
        for (int kh = 0; kh < 3; kh++) {
            const int hhr = h + kh - 1;
            if (hhr < 0 || hhr >= HH) continue;        // block-uniform skip
            __syncthreads();                            // prev mma done

            // ---- fill A slab (hi/lo bf16), rows r -> x[r-1], pair-packed ----
            const float* src = volb + (size_t)dd*HW + hhr*WW;
            for (int u = tid; u < AROWS*16; u += 512) {
                int r = u >> 4, ic0 = (u & 15) * 2;
                int w = r - 1;
                float x0 = 0.f, x1 = 0.f;
                if (w >= 0 && w < WW) {
                    x0 = src[(size_t)ic0*DHW + w];
                    x1 = src[(size_t)(ic0+1)*DHW + w];
                }
                __nv_bfloat16 h0 = __float2bfloat16_rn(x0);
                __nv_bfloat16 h1 = __float2bfloat16_rn(x1);
                __nv_bfloat16 l0 = __float2bfloat16_rn(x0 - __bfloat162float(h0));
                __nv_bfloat16 l1 = __float2bfloat16_rn(x1 - __bfloat162float(h1));
                uint32_t hp = ((uint32_t)__bfloat16_as_ushort(h1) << 16) |
                               (uint32_t)__bfloat16_as_ushort(h0);
                uint32_t lp = ((uint32_t)__bfloat16_as_ushort(l1) << 16) |
                               (uint32_t)__bfloat16_as_ushort(l0);
                int off = (r*ASTRIDE + ic0) * 2;
                *(uint32_t*)(smc + SA_H + off) = hp;
                *(uint32_t*)(smc + SA_L + off) = lp;
            }
            // ---- fill B: [hi/lo][kw][ic][oc] bf16 ----
            const int kbase = kd*9 + kh*3;
            for (int u = tid; u < 3*32*16; u += 512) {
                int kw = u >> 9, ic = (u >> 4) & 31, oc0 = (u & 15) * 2;
                float x0 = w1[(size_t)oc0*864 + ic*27 + kbase + kw];
                float x1 = w1[(size_t)(oc0+1)*864 + ic*27 + kbase + kw];
                __nv_bfloat16 h0 = __float2bfloat16_rn(x0);
                __nv_bfloat16 h1 = __float2bfloat16_rn(x1);
                __nv_bfloat16 l0 = __float2bfloat16_rn(x0 - __bfloat162float(h0));
                __nv_bfloat16 l1 = __float2bfloat16_rn(x1 - __bfloat162float(h1));
                uint32_t hp = ((uint32_t)__bfloat16_as_ushort(h1) << 16) |
                               (uint32_t)__bfloat16_as_ushort(h0);
                uint32_t lp = ((uint32_t)__bfloat16_as_ushort(l1) << 16) |
                               (uint32_t)__bfloat16_as_ushort(l0);
                int offh = SB_OFF + ((0*3 + kw)*32 + ic)*ASTRIDE*2 + oc0*2;
                int offl = SB_OFF + ((1*3 + kw)*32 + ic)*ASTRIDE*2 + oc0*2;
                *(uint32_t*)(smc + offh) = hp;
                *(uint32_t*)(smc + offl) = lp;
            }
            __syncthreads();

            // ---- mma: 3 passes (AhBh, AhBl, AlBh) x 3 kw x 2 k-steps ----
            #pragma unroll
            for (int pass = 0; pass < 3; pass++) {
                const uint32_t abase = sb + (pass < 2 ? SA_H : SA_L);
                const uint32_t bbase = sb + SB_OFF + (pass == 1 ? 3*32*ASTRIDE*2 : 0);
                #pragma unroll
                for (int kw = 0; kw < 3; kw++) {
                    #pragma unroll
                    for (int ks = 0; ks < 2; ks++) {
                        uint32_t a[4];
                        ldsm_x4(a, abase +
                            2*(((uint32_t)(m0 + kw) + lrow)*ASTRIDE + ks*16 + lcol));
                        #pragma unroll
                        for (int np = 0; np < 2; np++) {
                            uint32_t bq[4];
                            ldsm_x4_t(bq, bbase +
                                2*(((uint32_t)kw*32 + ks*16 + lrow)*ASTRIDE
                                   + np*16 + lcol));
                            mma_bf16(acc[np*2    ], a, bq[0], bq[1]);
                            mma_bf16(acc[np*2 + 1], a, bq[2], bq[3]);
                        }
                    }
                }
            }
        }
    }
    __syncthreads();

    // ---- epilogue: BN + ReLU from accumulator registers, masked store ----
    const int gr = t >> 2, qc = (t & 3) * 2;
    float* dstb = g_vol2 + (size_t)b*G*DHW + (size_t)d*HW + h*WW;
    #pragma unroll
    for (int n = 0; n < 4; n++) {
        #pragma unroll
        for (int half = 0; half < 2; half++) {
            const int w = m0 + gr + half*8;
            if (w < WW) {
                #pragma unroll
                for (int j = 0; j < 2; j++) {
                    const int oc = n*8 + qc + j;
                    float v = acc[n][half*2 + j];
                    v = fmaf(v, sBN[oc], sBN[32 + oc]);
                    dstb[(size_t)oc*DHW + w] = v > 0.f ? v : 0.f;
                }
            }
        }
    }
}

// ---------------------------------------------------------------------------
// Kernel 3: Conv3d(32->1, k=3, pad=1) -> logits (unchanged, known-good)
// ---------------------------------------------------------------------------
#define SLAB 244
__global__ void __launch_bounds__(256) conv2_kernel(const float* __restrict__ w2) {
    __shared__ float sW2[864];
    __shared__ float sIn[32*SLAB];

    const int h = blockIdx.x, d = blockIdx.y, b = blockIdx.z;
    const int tid = threadIdx.x;
    const int w = tid;

    for (int i = tid; i < 864; i += 256) sW2[i] = w2[i];

    float a0 = 0.f, a1 = 0.f, a2 = 0.f;
    for (int kd = 0; kd < 3; kd++) {
        const int dd = d + kd - 1;
        if (dd < 0 || dd >= DD) continue;
        for (int kh = 0; kh < 3; kh++) {
            const int hhr = h + kh - 1;
            if (hhr < 0 || hhr >= HH) continue;
            __syncthreads();
            const float* src = g_vol2 + (size_t)b*G*DHW + (size_t)dd*HW + hhr*WW;
            for (int i = tid; i < 32*242; i += 256) {
                int ic = i / 242, j = i % 242;
                int ww = j - 1;
                sIn[ic*SLAB + j] = (ww >= 0 && ww < WW) ? src[ic*DHW + ww] : 0.f;
            }
            __syncthreads();
            const int kbase = kd*9 + kh*3;
            if (w < WW) {
                #pragma unroll 8
                for (int ic = 0; ic < 32; ic++) {
                    a0 = fmaf(sW2[ic*27 + kbase    ], sIn[ic*SLAB + w    ], a0);
                    a1 = fmaf(sW2[ic*27 + kbase + 1], sIn[ic*SLAB + w + 1], a1);
                    a2 = fmaf(sW2[ic*27 + kbase + 2], sIn[ic*SLAB + w + 2], a2);
                }
            }
        }
    }
    if (w < WW)
        g_logits[((size_t)b*DD + d)*HW + h*WW + w] = a0 + a1 + a2;
}

// ---------------------------------------------------------------------------
// Kernel 4: softmax over D + disparity expectation (unchanged)
// ---------------------------------------------------------------------------
__global__ void __launch_bounds__(256) softmax_kernel(float* __restrict__ out) {
    const int h = blockIdx.x, b = blockIdx.y;
    const int w = threadIdx.x;
    if (w >= WW) return;
    const float* p = g_logits + (size_t)b*DHW + h*WW + w;
    float m = -1e30f;
    #pragma unroll 4
    for (int d = 0; d < DD; d++) m = fmaxf(m, p[d*HW]);
    float s = 0.f, e = 0.f;
    #pragma unroll 4
    for (int d = 0; d < DD; d++) {
        float t = __expf(p[d*HW] - m);
        s += t;
        e += t * (float)d;
    }
    out[(size_t)b*HW + h*WW + w] = e / s;
}

// ---------------------------------------------------------------------------
extern "C" void kernel_launch(void* const* d_in, const int* in_sizes, int n_in,
                              void* d_out, int out_size) {
    const float* fl    = (const float*)d_in[0];
    const float* fr    = (const float*)d_in[1];
    const float* w1    = (const float*)d_in[2];
    const float* gamma = (const float*)d_in[3];
    const float* beta  = (const float*)d_in[4];
    const float* mean  = (const float*)d_in[5];
    const float* var   = (const float*)d_in[6];
    const float* w2    = (const float*)d_in[7];
    float* out = (float*)d_out;

    cudaFuncSetAttribute(conv1_mma_kernel,
                         cudaFuncAttributeMaxDynamicSharedMemorySize,
                         (int)CONV1_SMEM);

    vol_kernel      <<<dim3(HH, G,  BB), 256>>>(fl, fr);
    conv1_mma_kernel<<<dim3(HH, DD, BB), 512, CONV1_SMEM>>>(w1, gamma, beta, mean, var);
    conv2_kernel    <<<dim3(HH, DD, BB), 256>>>(w2);
    softmax_kernel  <<<dim3(HH, BB), 256>>>(out);
}

// round 7
// speedup vs baseline: 2.7095x; 1.3506x over previous
#include <cuda_runtime.h>
#include <cuda_bf16.h>
#include <cstdint>

#define BB  4
#define CIN 320
#define G   32
#define CPG 10
#define DD  48
#define HH  72
#define WW  240
#define HW  (HH*WW)          // 17280
#define DHW (DD*HW)          // 829440
#define VOL_ELEMS (BB*G*DHW) // 106,168,320

// Scratch (allocation-free: device globals)
__device__ float g_vol   [VOL_ELEMS];   // [B][G=ic][D][H][W]  gwc cost volume
__device__ float g_vol2  [VOL_ELEMS];   // [B][32oc][D][H][W]  conv1+BN+ReLU
__device__ float g_logits[BB*DHW];      // [B][D][H][W]
// MMA-native transposed bf16 hi/lo planes: [B][D][H][W][ic]
__device__ __align__(16) uint16_t g_volT_h[VOL_ELEMS];
__device__ __align__(16) uint16_t g_volT_l[VOL_ELEMS];
// Repacked conv1 weights: [k=kd*9+kh*3+kw][ic][oc] bf16 hi/lo
__device__ __align__(16) uint16_t g_w1T_h[27*32*32];
__device__ __align__(16) uint16_t g_w1T_l[27*32*32];

// ===========================================================================
// sm_80-ISA tensor-core helpers (valid on baseline sm_100 target)
// ===========================================================================
__device__ __forceinline__ uint32_t smem_to_u32(const void* p) {
    uint32_t a;
    asm("{ .reg .u64 t; cvta.to.shared.u64 t, %1; cvt.u32.u64 %0, t; }"
        : "=r"(a) : "l"(p));
    return a;
}
__device__ __forceinline__ void ldsm_x4(uint32_t* r, uint32_t addr) {
    asm volatile("ldmatrix.sync.aligned.m8n8.x4.shared.b16 {%0,%1,%2,%3}, [%4];"
        : "=r"(r[0]), "=r"(r[1]), "=r"(r[2]), "=r"(r[3]) : "r"(addr));
}
__device__ __forceinline__ void ldsm_x4_t(uint32_t* r, uint32_t addr) {
    asm volatile("ldmatrix.sync.aligned.m8n8.x4.trans.shared.b16 {%0,%1,%2,%3}, [%4];"
        : "=r"(r[0]), "=r"(r[1]), "=r"(r[2]), "=r"(r[3]) : "r"(addr));
}
__device__ __forceinline__ void mma_bf16(float* d, const uint32_t* a,
                                         uint32_t b0, uint32_t b1) {
    asm volatile(
        "mma.sync.aligned.m16n8k16.row.col.f32.bf16.bf16.f32 "
        "{%0,%1,%2,%3}, {%4,%5,%6,%7}, {%8,%9}, {%0,%1,%2,%3};"
        : "+f"(d[0]), "+f"(d[1]), "+f"(d[2]), "+f"(d[3])
        : "r"(a[0]), "r"(a[1]), "r"(a[2]), "r"(a[3]), "r"(b0), "r"(b1));
}

// ---------------------------------------------------------------------------
// Kernel 1: groupwise-correlation cost volume (unchanged, known-good)
// ---------------------------------------------------------------------------
__global__ void __launch_bounds__(256) vol_kernel(const float* __restrict__ fl,
                                                  const float* __restrict__ fr) {
    __shared__ float sFl[CPG][WW];
    __shared__ float sFr[CPG][WW];
    const int h = blockIdx.x, g = blockIdx.y, b = blockIdx.z;
    const int tid = threadIdx.x;

    const float* flb = fl + ((size_t)b*CIN + g*CPG)*HW + h*WW;
    const float* frb = fr + ((size_t)b*CIN + g*CPG)*HW + h*WW;
    for (int i = tid; i < CPG*WW; i += 256) {
        int c = i / WW, w = i % WW;
        sFl[c][w] = flb[c*HW + w];
        sFr[c][w] = frb[c*HW + w];
    }
    __syncthreads();

    float* dst = g_vol + ((size_t)b*G + g)*DHW + h*WW;
    for (int i = tid; i < DD*WW; i += 256) {
        int d = i / WW, w = i % WW;
        float v = 0.f;
        if (w >= d) {
            float s = 0.f;
            #pragma unroll
            for (int c = 0; c < CPG; c++) s += sFl[c][w] * sFr[c][w-d];
            v = s * (1.0f/CPG);
        }
        dst[d*HW + w] = v;
    }
}

// ---------------------------------------------------------------------------
// Kernel 1b: transpose g_vol -> g_volT_{h,l}: [b][d][h][w][ic] bf16 hi/lo.
// Coalesced read ([ic][w] rows), smem tile (stride 241 = odd -> conflict-free),
// coalesced write (w-major, 32 ic x 2B contiguous).
// ---------------------------------------------------------------------------
__global__ void __launch_bounds__(256) volT_kernel() {
    __shared__ float sT[32*241];
    const int h = blockIdx.x, d = blockIdx.y, b = blockIdx.z;
    const int tid = threadIdx.x;

    const float* src = g_vol + (size_t)b*G*DHW + (size_t)d*HW + h*WW;
    for (int i = tid; i < 32*240; i += 256) {
        int ic = i / 240, w = i - ic*240;
        sT[ic*241 + w] = src[(size_t)ic*DHW + w];
    }
    __syncthreads();

    const size_t base = (size_t)(((b*DD + d)*HH + h))*WW*32;
    uint16_t* __restrict__ dh = g_volT_h + base;
    uint16_t* __restrict__ dl = g_volT_l + base;
    for (int i = tid; i < 240*32; i += 256) {
        int w = i >> 5, ic = i & 31;
        float x = sT[ic*241 + w];
        __nv_bfloat16 xh = __float2bfloat16_rn(x);
        __nv_bfloat16 xl = __float2bfloat16_rn(x - __bfloat162float(xh));
        dh[i] = __bfloat16_as_ushort(xh);
        dl[i] = __bfloat16_as_ushort(xl);
    }
}

// ---------------------------------------------------------------------------
// Kernel 1c: repack w1 -> g_w1T_{h,l}[k][ic][oc] bf16 hi/lo (tiny, one block)
// ---------------------------------------------------------------------------
__global__ void __launch_bounds__(512) w1T_kernel(const float* __restrict__ w1) {
    const int tid = threadIdx.x;
    for (int i = tid; i < 27*32*32; i += 512) {
        int k = i >> 10, ic = (i >> 5) & 31, oc = i & 31;
        float x = w1[(size_t)oc*864 + ic*27 + k];
        __nv_bfloat16 xh = __float2bfloat16_rn(x);
        __nv_bfloat16 xl = __float2bfloat16_rn(x - __bfloat162float(xh));
        g_w1T_h[i] = __bfloat16_as_ushort(xh);
        g_w1T_l[i] = __bfloat16_as_ushort(xl);
    }
}

// ---------------------------------------------------------------------------
// Kernel 2: Conv3d(32->32,k3,p1)+BN+ReLU via mma.sync bf16, 3-pass hi/lo.
// Identical math/mma structure to the R6 passing kernel; stage fills are now
// pure vectorized copies from the pre-transposed/pre-converted tensors.
// ---------------------------------------------------------------------------
#define ASTRIDE 40
#define AROWS   264
#define SA_H    0
#define SA_L    (AROWS*ASTRIDE*2)            // 21120
#define SB_OFF  (2*AROWS*ASTRIDE*2)          // 42240
#define SB_SIZE (2*3*32*ASTRIDE*2)           // 15360
#define SBN_OFF (SB_OFF + SB_SIZE)           // 57600
#define CONV1_SMEM (SBN_OFF + 256)           // 57856

__global__ void __launch_bounds__(512)
conv1_mma_kernel(const float* __restrict__ gamma, const float* __restrict__ beta,
                 const float* __restrict__ mean, const float* __restrict__ var) {
    extern __shared__ char smc[];
    const uint32_t sb = smem_to_u32(smc);
    float* sBN = (float*)(smc + SBN_OFF);    // sc[32], sh[32]

    const int tid = threadIdx.x, wid = tid >> 5, t = tid & 31;
    const int h = blockIdx.x, d = blockIdx.y, b = blockIdx.z;
    const int m0 = wid * 16;
    const uint32_t lrow = (uint32_t)(t & 15);
    const uint32_t lcol = (uint32_t)((t & 16) >> 1);   // 0 or 8

    if (tid < 32) {
        float sc = gamma[tid] * rsqrtf(var[tid] + 1e-5f);
        sBN[tid] = sc;
        sBN[32 + tid] = beta[tid] - mean[tid] * sc;
    }

    float acc[4][4];
    #pragma unroll
    for (int n = 0; n < 4; n++)
        #pragma unroll
        for (int j = 0; j < 4; j++) acc[n][j] = 0.f;

    for (int kd = 0; kd < 3; kd++) {
        const int dd = d + kd - 1;
        if (dd < 0 || dd >= DD) continue;
        for (int kh = 0; kh < 3; kh++) {
            const int hhr = h + kh - 1;
            if (hhr < 0 || hhr >= HH) continue;        // block-uniform skip
            __syncthreads();                            // prev stage mma done

            // ---- A fill: vectorized copy from g_volT (row w -> slab row w+1)
            const size_t abase = (size_t)(((b*DD + dd)*HH + hhr))*WW*32;
            const uint16_t* __restrict__ srcH = g_volT_h + abase;
            const uint16_t* __restrict__ srcL = g_volT_l + abase;
            for (int u = tid; u < 2*AROWS*4; u += 512) {
                const int plane = (u >= AROWS*4);
                const int v = plane ? u - AROWS*4 : u;
                const int r = v >> 2, q = v & 3;
                const int w = r - 1;
                uint4 val = make_uint4(0u, 0u, 0u, 0u);
                if (w >= 0 && w < WW) {
                    const uint16_t* sp = (plane ? srcL : srcH) + (size_t)w*32 + q*8;
                    val = *(const uint4*)sp;
                }
                *(uint4*)(smc + (plane ? SA_L : SA_H) + (r*ASTRIDE + q*8)*2) = val;
            }
            // ---- B fill: contiguous copy from g_w1T (L2-hot) ----
            const int kbase = kd*9 + kh*3;
            for (int u = tid; u < 2*3*32*4; u += 512) {
                const int plane = (u >= 3*32*4);
                const int v = plane ? u - 3*32*4 : u;
                const int kw = v >> 7, rest = v & 127;
                const int ic = rest >> 2, q = rest & 3;
                const uint16_t* sp = (plane ? g_w1T_l : g_w1T_h)
                                     + ((kbase + kw)*32 + ic)*32 + q*8;
                uint4 val = *(const uint4*)sp;
                *(uint4*)(smc + SB_OFF + ((plane*3 + kw)*32 + ic)*ASTRIDE*2 + q*16) = val;
            }
            __syncthreads();

            // ---- mma: 3 passes (AhBh, AhBl, AlBh) x 3 kw x 2 k-steps ----
            #pragma unroll
            for (int pass = 0; pass < 3; pass++) {
                const uint32_t abse = sb + (pass < 2 ? SA_H : SA_L);
                const uint32_t bbse = sb + SB_OFF + (pass == 1 ? 3*32*ASTRIDE*2 : 0);
                #pragma unroll
                for (int kw = 0; kw < 3; kw++) {
                    #pragma unroll
                    for (int ks = 0; ks < 2; ks++) {
                        uint32_t a[4];
                        ldsm_x4(a, abse +
                            2*(((uint32_t)(m0 + kw) + lrow)*ASTRIDE + ks*16 + lcol));
                        #pragma unroll
                        for (int np = 0; np < 2; np++) {
                            uint32_t bq[4];
                            ldsm_x4_t(bq, bbse +
                                2*(((uint32_t)kw*32 + ks*16 + lrow)*ASTRIDE
                                   + np*16 + lcol));
                            mma_bf16(acc[np*2    ], a, bq[0], bq[1]);
                            mma_bf16(acc[np*2 + 1], a, bq[2], bq[3]);
                        }
                    }
                }
            }
        }
    }
    __syncthreads();

    // ---- epilogue: BN + ReLU from accumulator registers, masked store ----
    const int gr = t >> 2, qc = (t & 3) * 2;
    float* dstb = g_vol2 + (size_t)b*G*DHW + (size_t)d*HW + h*WW;
    #pragma unroll
    for (int n = 0; n < 4; n++) {
        #pragma unroll
        for (int half = 0; half < 2; half++) {
            const int w = m0 + gr + half*8;
            if (w < WW) {
                #pragma unroll
                for (int j = 0; j < 2; j++) {
                    const int oc = n*8 + qc + j;
                    float v = acc[n][half*2 + j];
                    v = fmaf(v, sBN[oc], sBN[32 + oc]);
                    dstb[(size_t)oc*DHW + w] = v > 0.f ? v : 0.f;
                }
            }
        }
    }
}

// ---------------------------------------------------------------------------
// Kernel 3: Conv3d(32->1, k=3, pad=1) -> logits (unchanged, known-good)
// ---------------------------------------------------------------------------
#define SLAB 244
__global__ void __launch_bounds__(256) conv2_kernel(const float* __restrict__ w2) {
    __shared__ float sW2[864];
    __shared__ float sIn[32*SLAB];

    const int h = blockIdx.x, d = blockIdx.y, b = blockIdx.z;
    const int tid = threadIdx.x;
    const int w = tid;

    for (int i = tid; i < 864; i += 256) sW2[i] = w2[i];

    float a0 = 0.f, a1 = 0.f, a2 = 0.f;
    for (int kd = 0; kd < 3; kd++) {
        const int dd = d + kd - 1;
        if (dd < 0 || dd >= DD) continue;
        for (int kh = 0; kh < 3; kh++) {
            const int hhr = h + kh - 1;
            if (hhr < 0 || hhr >= HH) continue;
            __syncthreads();
            const float* src = g_vol2 + (size_t)b*G*DHW + (size_t)dd*HW + hhr*WW;
            for (int i = tid; i < 32*242; i += 256) {
                int ic = i / 242, j = i % 242;
                int ww = j - 1;
                sIn[ic*SLAB + j] = (ww >= 0 && ww < WW) ? src[ic*DHW + ww] : 0.f;
            }
            __syncthreads();
            const int kbase = kd*9 + kh*3;
            if (w < WW) {
                #pragma unroll 8
                for (int ic = 0; ic < 32; ic++) {
                    a0 = fmaf(sW2[ic*27 + kbase    ], sIn[ic*SLAB + w    ], a0);
                    a1 = fmaf(sW2[ic*27 + kbase + 1], sIn[ic*SLAB + w + 1], a1);
                    a2 = fmaf(sW2[ic*27 + kbase + 2], sIn[ic*SLAB + w + 2], a2);
                }
            }
        }
    }
    if (w < WW)
        g_logits[((size_t)b*DD + d)*HW + h*WW + w] = a0 + a1 + a2;
}

// ---------------------------------------------------------------------------
// Kernel 4: softmax over D + disparity expectation (unchanged)
// ---------------------------------------------------------------------------
__global__ void __launch_bounds__(256) softmax_kernel(float* __restrict__ out) {
    const int h = blockIdx.x, b = blockIdx.y;
    const int w = threadIdx.x;
    if (w >= WW) return;
    const float* p = g_logits + (size_t)b*DHW + h*WW + w;
    float m = -1e30f;
    #pragma unroll 4
    for (int d = 0; d < DD; d++) m = fmaxf(m, p[d*HW]);
    float s = 0.f, e = 0.f;
    #pragma unroll 4
    for (int d = 0; d < DD; d++) {
        float t = __expf(p[d*HW] - m);
        s += t;
        e += t * (float)d;
    }
    out[(size_t)b*HW + h*WW + w] = e / s;
}

// ---------------------------------------------------------------------------
extern "C" void kernel_launch(void* const* d_in, const int* in_sizes, int n_in,
                              void* d_out, int out_size) {
    const float* fl    = (const float*)d_in[0];
    const float* fr    = (const float*)d_in[1];
    const float* w1    = (const float*)d_in[2];
    const float* gamma = (const float*)d_in[3];
    const float* beta  = (const float*)d_in[4];
    const float* mean  = (const float*)d_in[5];
    const float* var   = (const float*)d_in[6];
    const float* w2    = (const float*)d_in[7];
    float* out = (float*)d_out;

    cudaFuncSetAttribute(conv1_mma_kernel,
                         cudaFuncAttributeMaxDynamicSharedMemorySize,
                         (int)CONV1_SMEM);

    vol_kernel      <<<dim3(HH, G,  BB), 256>>>(fl, fr);
    volT_kernel     <<<dim3(HH, DD, BB), 256>>>();
    w1T_kernel      <<<1, 512>>>(w1);
    conv1_mma_kernel<<<dim3(HH, DD, BB), 512, CONV1_SMEM>>>(gamma, beta, mean, var);
    conv2_kernel    <<<dim3(HH, DD, BB), 256>>>(w2);
    softmax_kernel  <<<dim3(HH, BB), 256>>>(out);
}

// round 8
// speedup vs baseline: 3.8172x; 1.4088x over previous
#include <cuda_runtime.h>
#include <cuda_bf16.h>
#include <cstdint>

#define BB  4
#define CIN 320
#define G   32
#define CPG 10
#define DD  48
#define HH  72
#define WW  240
#define HW  (HH*WW)          // 17280
#define DHW (DD*HW)          // 829440
#define VOL_ELEMS (BB*G*DHW) // 106,168,320

// Scratch (allocation-free: device globals)
__device__ float g_vol   [VOL_ELEMS];   // [B][G=ic][D][H][W]  gwc cost volume
__device__ float g_vol2  [VOL_ELEMS];   // [B][32oc][D][H][W]  conv1+BN+ReLU
__device__ float g_logits[BB*DHW];      // [B][D][H][W]
// MMA-native transposed bf16 hi/lo planes: [B][D][H][W][ic]
__device__ __align__(16) uint16_t g_volT_h[VOL_ELEMS];
__device__ __align__(16) uint16_t g_volT_l[VOL_ELEMS];
// Repacked conv1 weights: [k=kd*9+kh*3+kw][ic][oc] bf16 hi/lo
__device__ __align__(16) uint16_t g_w1T_h[27*32*32];
__device__ __align__(16) uint16_t g_w1T_l[27*32*32];

// ===========================================================================
// sm_80-ISA helpers (valid on baseline sm_100 target)
// ===========================================================================
__device__ __forceinline__ uint32_t smem_to_u32(const void* p) {
    uint32_t a;
    asm("{ .reg .u64 t; cvta.to.shared.u64 t, %1; cvt.u32.u64 %0, t; }"
        : "=r"(a) : "l"(p));
    return a;
}
__device__ __forceinline__ void ldsm_x4(uint32_t* r, uint32_t addr) {
    asm volatile("ldmatrix.sync.aligned.m8n8.x4.shared.b16 {%0,%1,%2,%3}, [%4];"
        : "=r"(r[0]), "=r"(r[1]), "=r"(r[2]), "=r"(r[3]) : "r"(addr));
}
__device__ __forceinline__ void ldsm_x4_t(uint32_t* r, uint32_t addr) {
    asm volatile("ldmatrix.sync.aligned.m8n8.x4.trans.shared.b16 {%0,%1,%2,%3}, [%4];"
        : "=r"(r[0]), "=r"(r[1]), "=r"(r[2]), "=r"(r[3]) : "r"(addr));
}
__device__ __forceinline__ void mma_bf16(float* d, const uint32_t* a,
                                         uint32_t b0, uint32_t b1) {
    asm volatile(
        "mma.sync.aligned.m16n8k16.row.col.f32.bf16.bf16.f32 "
        "{%0,%1,%2,%3}, {%4,%5,%6,%7}, {%8,%9}, {%0,%1,%2,%3};"
        : "+f"(d[0]), "+f"(d[1]), "+f"(d[2]), "+f"(d[3])
        : "r"(a[0]), "r"(a[1]), "r"(a[2]), "r"(a[3]), "r"(b0), "r"(b1));
}
__device__ __forceinline__ void cpasync16(uint32_t dst, const void* src,
                                          uint32_t srcsize) {
    asm volatile("cp.async.cg.shared.global [%0], [%1], 16, %2;"
        :: "r"(dst), "l"(src), "r"(srcsize));
}
__device__ __forceinline__ void cpasync_commit() {
    asm volatile("cp.async.commit_group;" ::: "memory");
}
#define CPASYNC_WAIT1() asm volatile("cp.async.wait_group 1;" ::: "memory")

// ---------------------------------------------------------------------------
// Kernel 1: groupwise-correlation cost volume (unchanged, known-good)
// ---------------------------------------------------------------------------
__global__ void __launch_bounds__(256) vol_kernel(const float* __restrict__ fl,
                                                  const float* __restrict__ fr) {
    __shared__ float sFl[CPG][WW];
    __shared__ float sFr[CPG][WW];
    const int h = blockIdx.x, g = blockIdx.y, b = blockIdx.z;
    const int tid = threadIdx.x;

    const float* flb = fl + ((size_t)b*CIN + g*CPG)*HW + h*WW;
    const float* frb = fr + ((size_t)b*CIN + g*CPG)*HW + h*WW;
    for (int i = tid; i < CPG*WW; i += 256) {
        int c = i / WW, w = i % WW;
        sFl[c][w] = flb[c*HW + w];
        sFr[c][w] = frb[c*HW + w];
    }
    __syncthreads();

    float* dst = g_vol + ((size_t)b*G + g)*DHW + h*WW;
    for (int i = tid; i < DD*WW; i += 256) {
        int d = i / WW, w = i % WW;
        float v = 0.f;
        if (w >= d) {
            float s = 0.f;
            #pragma unroll
            for (int c = 0; c < CPG; c++) s += sFl[c][w] * sFr[c][w-d];
            v = s * (1.0f/CPG);
        }
        dst[d*HW + w] = v;
    }
}

// ---------------------------------------------------------------------------
// Kernel 1b: transpose g_vol -> g_volT_{h,l}: [b][d][h][w][ic] bf16 hi/lo.
// ---------------------------------------------------------------------------
__global__ void __launch_bounds__(256) volT_kernel() {
    __shared__ float sT[32*241];
    const int h = blockIdx.x, d = blockIdx.y, b = blockIdx.z;
    const int tid = threadIdx.x;

    const float* src = g_vol + (size_t)b*G*DHW + (size_t)d*HW + h*WW;
    for (int i = tid; i < 32*240; i += 256) {
        int ic = i / 240, w = i - ic*240;
        sT[ic*241 + w] = src[(size_t)ic*DHW + w];
    }
    __syncthreads();

    const size_t base = (size_t)(((b*DD + d)*HH + h))*WW*32;
    uint16_t* __restrict__ dh = g_volT_h + base;
    uint16_t* __restrict__ dl = g_volT_l + base;
    for (int i = tid; i < 240*32; i += 256) {
        int w = i >> 5, ic = i & 31;
        float x = sT[ic*241 + w];
        __nv_bfloat16 xh = __float2bfloat16_rn(x);
        __nv_bfloat16 xl = __float2bfloat16_rn(x - __bfloat162float(xh));
        dh[i] = __bfloat16_as_ushort(xh);
        dl[i] = __bfloat16_as_ushort(xl);
    }
}

// ---------------------------------------------------------------------------
// Kernel 1c: repack w1 -> g_w1T_{h,l}[k][ic][oc] bf16 hi/lo (tiny, one block)
// ---------------------------------------------------------------------------
__global__ void __launch_bounds__(512) w1T_kernel(const float* __restrict__ w1) {
    const int tid = threadIdx.x;
    for (int i = tid; i < 27*32*32; i += 512) {
        int k = i >> 10, ic = (i >> 5) & 31, oc = i & 31;
        float x = w1[(size_t)oc*864 + ic*27 + k];
        __nv_bfloat16 xh = __float2bfloat16_rn(x);
        __nv_bfloat16 xl = __float2bfloat16_rn(x - __bfloat162float(xh));
        g_w1T_h[i] = __bfloat16_as_ushort(xh);
        g_w1T_l[i] = __bfloat16_as_ushort(xl);
    }
}

// ---------------------------------------------------------------------------
// Kernel 2: Conv3d(32->32,k3,p1)+BN+ReLU via mma.sync bf16, 3-product hi/lo.
// cp.async double-buffered stage pipeline + A-fragment-dedup'd mma loop.
// ---------------------------------------------------------------------------
#define ASTRIDE 40
#define AROWS   264
#define STG_A_H 0
#define STG_A_L (AROWS*ASTRIDE*2)            // 21120
#define STG_B   (2*AROWS*ASTRIDE*2)          // 42240
#define STG_SIZE (STG_B + 2*3*32*ASTRIDE*2)  // 57600 per buffer
#define SBN_OFF (2*STG_SIZE)                 // 115200
#define CONV1_SMEM (SBN_OFF + 256)           // 115456

__device__ __forceinline__ void fill_stage(uint32_t sbuf, size_t abase,
                                           int kbase, int tid) {
    // A: 2 planes x 264 rows x 4 chunks of 16B (slab row r -> input w = r-1)
    #pragma unroll 1
    for (int u = tid; u < 2*AROWS*4; u += 512) {
        const int plane = (u >= AROWS*4);
        const int v = plane ? u - AROWS*4 : u;
        const int r = v >> 2, q = v & 3;
        const int w = r - 1;
        const int ok = (w >= 0 && w < WW);
        const uint16_t* sp = (plane ? g_volT_l : g_volT_h) + abase
                             + (size_t)(ok ? w : 0)*32 + q*8;
        cpasync16(sbuf + (plane ? STG_A_L : STG_A_H) + (r*ASTRIDE + q*8)*2,
                  sp, ok ? 16u : 0u);
    }
    // B: 2 planes x 3 kw x 32 ic x 4 chunks of 16B (contiguous, L2-hot)
    #pragma unroll 1
    for (int u = tid; u < 2*3*32*4; u += 512) {
        const int plane = (u >= 3*32*4);
        const int v = plane ? u - 3*32*4 : u;
        const int kw = v >> 7, rest = v & 127;
        const int ic = rest >> 2, q = rest & 3;
        const uint16_t* sp = (plane ? g_w1T_l : g_w1T_h)
                             + ((kbase + kw)*32 + ic)*32 + q*8;
        cpasync16(sbuf + STG_B + ((plane*3 + kw)*32 + ic)*ASTRIDE*2 + q*16,
                  sp, 16u);
    }
}

__global__ void __launch_bounds__(512)
conv1_mma_kernel(const float* __restrict__ gamma, const float* __restrict__ beta,
                 const float* __restrict__ mean, const float* __restrict__ var) {
    extern __shared__ char smc[];
    const uint32_t sb = smem_to_u32(smc);
    float* sBN = (float*)(smc + SBN_OFF);    // sc[32], sh[32]

    const int tid = threadIdx.x, wid = tid >> 5, t = tid & 31;
    const int h = blockIdx.x, d = blockIdx.y, b = blockIdx.z;
    const int m0 = wid * 16;
    const uint32_t lrow = (uint32_t)(t & 15);
    const uint32_t lcol = (uint32_t)((t & 16) >> 1);   // 0 or 8

    if (tid < 32) {
        float sc = gamma[tid] * rsqrtf(var[tid] + 1e-5f);
        sBN[tid] = sc;
        sBN[32 + tid] = beta[tid] - mean[tid] * sc;
    }

    float acc[4][4];
    #pragma unroll
    for (int n = 0; n < 4; n++)
        #pragma unroll
        for (int j = 0; j < 4; j++) acc[n][j] = 0.f;

    // ---- enumerate valid (kd,kh) stages ----
    size_t sab[9]; int skb[9]; int nst = 0;
    for (int kd = 0; kd < 3; kd++) {
        const int dd = d + kd - 1;
        if (dd < 0 || dd >= DD) continue;
        for (int kh = 0; kh < 3; kh++) {
            const int hhr = h + kh - 1;
            if (hhr < 0 || hhr >= HH) continue;
            sab[nst] = (size_t)(((b*DD + dd)*HH + hhr))*WW*32;
            skb[nst] = kd*9 + kh*3;
            nst++;
        }
    }

    // ---- software pipeline: prefetch s+1 while mma s ----
    fill_stage(sb, sab[0], skb[0], tid);
    cpasync_commit();

    for (int s = 0; s < nst; s++) {
        if (s + 1 < nst)
            fill_stage(sb + ((s + 1) & 1)*STG_SIZE, sab[s+1], skb[s+1], tid);
        cpasync_commit();
        CPASYNC_WAIT1();                 // stage s fill complete
        __syncthreads();

        const uint32_t ab = sb + (s & 1)*STG_SIZE;
        const uint32_t aH = ab + STG_A_H, aL = ab + STG_A_L, bB = ab + STG_B;
        #pragma unroll
        for (int kw = 0; kw < 3; kw++) {
            #pragma unroll
            for (int ks = 0; ks < 2; ks++) {
                const uint32_t aoff =
                    2*(((uint32_t)(m0 + kw) + lrow)*ASTRIDE + ks*16 + lcol);
                uint32_t Ah[4], Al[4];
                ldsm_x4(Ah, aH + aoff);
                ldsm_x4(Al, aL + aoff);
                #pragma unroll
                for (int np = 0; np < 2; np++) {
                    const uint32_t boff =
                        2*(((uint32_t)kw*32 + ks*16 + lrow)*ASTRIDE + np*16 + lcol);
                    uint32_t Bh[4], Bl[4];
                    ldsm_x4_t(Bh, bB + boff);
                    ldsm_x4_t(Bl, bB + 3*32*ASTRIDE*2 + boff);
                    mma_bf16(acc[np*2    ], Ah, Bh[0], Bh[1]);
                    mma_bf16(acc[np*2 + 1], Ah, Bh[2], Bh[3]);
                    mma_bf16(acc[np*2    ], Ah, Bl[0], Bl[1]);
                    mma_bf16(acc[np*2 + 1], Ah, Bl[2], Bl[3]);
                    mma_bf16(acc[np*2    ], Al, Bh[0], Bh[1]);
                    mma_bf16(acc[np*2 + 1], Al, Bh[2], Bh[3]);
                }
            }
        }
        __syncthreads();                 // protect buffer before next overwrite
    }

    // ---- epilogue: BN + ReLU from accumulator registers, masked store ----
    const int gr = t >> 2, qc = (t & 3) * 2;
    float* dstb = g_vol2 + (size_t)b*G*DHW + (size_t)d*HW + h*WW;
    #pragma unroll
    for (int n = 0; n < 4; n++) {
        #pragma unroll
        for (int half = 0; half < 2; half++) {
            const int w = m0 + gr + half*8;
            if (w < WW) {
                #pragma unroll
                for (int j = 0; j < 2; j++) {
                    const int oc = n*8 + qc + j;
                    float v = acc[n][half*2 + j];
                    v = fmaf(v, sBN[oc], sBN[32 + oc]);
                    dstb[(size_t)oc*DHW + w] = v > 0.f ? v : 0.f;
                }
            }
        }
    }
}

// ---------------------------------------------------------------------------
// Kernel 3: Conv3d(32->1, k=3, pad=1) -> logits (unchanged, known-good)
// ---------------------------------------------------------------------------
#define SLAB 244
__global__ void __launch_bounds__(256) conv2_kernel(const float* __restrict__ w2) {
    __shared__ float sW2[864];
    __shared__ float sIn[32*SLAB];

    const int h = blockIdx.x, d = blockIdx.y, b = blockIdx.z;
    const int tid = threadIdx.x;
    const int w = tid;

    for (int i = tid; i < 864; i += 256) sW2[i] = w2[i];

    float a0 = 0.f, a1 = 0.f, a2 = 0.f;
    for (int kd = 0; kd < 3; kd++) {
        const int dd = d + kd - 1;
        if (dd < 0 || dd >= DD) continue;
        for (int kh = 0; kh < 3; kh++) {
            const int hhr = h + kh - 1;
            if (hhr < 0 || hhr >= HH) continue;
            __syncthreads();
            const float* src = g_vol2 + (size_t)b*G*DHW + (size_t)dd*HW + hhr*WW;
            for (int i = tid; i < 32*242; i += 256) {
                int ic = i / 242, j = i % 242;
                int ww = j - 1;
                sIn[ic*SLAB + j] = (ww >= 0 && ww < WW) ? src[ic*DHW + ww] : 0.f;
            }
            __syncthreads();
            const int kbase = kd*9 + kh*3;
            if (w < WW) {
                #pragma unroll 8
                for (int ic = 0; ic < 32; ic++) {
                    a0 = fmaf(sW2[ic*27 + kbase    ], sIn[ic*SLAB + w    ], a0);
                    a1 = fmaf(sW2[ic*27 + kbase + 1], sIn[ic*SLAB + w + 1], a1);
                    a2 = fmaf(sW2[ic*27 + kbase + 2], sIn[ic*SLAB + w + 2], a2);
                }
            }
        }
    }
    if (w < WW)
        g_logits[((size_t)b*DD + d)*HW + h*WW + w] = a0 + a1 + a2;
}

// ---------------------------------------------------------------------------
// Kernel 4: softmax over D + disparity expectation (unchanged)
// ---------------------------------------------------------------------------
__global__ void __launch_bounds__(256) softmax_kernel(float* __restrict__ out) {
    const int h = blockIdx.x, b = blockIdx.y;
    const int w = threadIdx.x;
    if (w >= WW) return;
    const float* p = g_logits + (size_t)b*DHW + h*WW + w;
    float m = -1e30f;
    #pragma unroll 4
    for (int d = 0; d < DD; d++) m = fmaxf(m, p[d*HW]);
    float s = 0.f, e = 0.f;
    #pragma unroll 4
    for (int d = 0; d < DD; d++) {
        float t = __expf(p[d*HW] - m);
        s += t;
        e += t * (float)d;
    }
    out[(size_t)b*HW + h*WW + w] = e / s;
}

// ---------------------------------------------------------------------------
extern "C" void kernel_launch(void* const* d_in, const int* in_sizes, int n_in,
                              void* d_out, int out_size) {
    const float* fl    = (const float*)d_in[0];
    const float* fr    = (const float*)d_in[1];
    const float* w1    = (const float*)d_in[2];
    const float* gamma = (const float*)d_in[3];
    const float* beta  = (const float*)d_in[4];
    const float* mean  = (const float*)d_in[5];
    const float* var   = (const float*)d_in[6];
    const float* w2    = (const float*)d_in[7];
    float* out = (float*)d_out;

    cudaFuncSetAttribute(conv1_mma_kernel,
                         cudaFuncAttributeMaxDynamicSharedMemorySize,
                         (int)CONV1_SMEM);

    vol_kernel      <<<dim3(HH, G,  BB), 256>>>(fl, fr);
    volT_kernel     <<<dim3(HH, DD, BB), 256>>>();
    w1T_kernel      <<<1, 512>>>(w1);
    conv1_mma_kernel<<<dim3(HH, DD, BB), 512, CONV1_SMEM>>>(gamma, beta, mean, var);
    conv2_kernel    <<<dim3(HH, DD, BB), 256>>>(w2);
    softmax_kernel  <<<dim3(HH, BB), 256>>>(out);
}

// round 10
// speedup vs baseline: 4.2566x; 1.1151x over previous
#include <cuda_runtime.h>
#include <cuda_bf16.h>
#include <cstdint>

#define BB  4
#define CIN 320
#define G   32
#define CPG 10
#define DD  48
#define HH  72
#define WW  240
#define HW  (HH*WW)          // 17280
#define DHW (DD*HW)          // 829440
#define VOL_ELEMS (BB*G*DHW) // 106,168,320

// Scratch (allocation-free: device globals)
__device__ float g_vol   [VOL_ELEMS];   // [B][G=ic][D][H][W]  gwc cost volume
__device__ __align__(16) float g_vol2T[VOL_ELEMS]; // [B][D][H][W][oc] conv1 out
__device__ float g_logits[BB*DHW];      // [B][D][H][W]
// MMA-native transposed bf16 hi/lo planes: [B][D][H][W][ic]
__device__ __align__(16) uint16_t g_volT_h[VOL_ELEMS];
__device__ __align__(16) uint16_t g_volT_l[VOL_ELEMS];
// Repacked conv1 weights: [k=kd*9+kh*3+kw][ic][oc] bf16 hi/lo
__device__ __align__(16) uint16_t g_w1T_h[27*32*32];
__device__ __align__(16) uint16_t g_w1T_l[27*32*32];

// ===========================================================================
// sm_80-ISA helpers (valid on baseline sm_100 target)
// ===========================================================================
__device__ __forceinline__ uint32_t smem_to_u32(const void* p) {
    uint32_t a;
    asm("{ .reg .u64 t; cvta.to.shared.u64 t, %1; cvt.u32.u64 %0, t; }"
        : "=r"(a) : "l"(p));
    return a;
}
__device__ __forceinline__ void ldsm_x4(uint32_t* r, uint32_t addr) {
    asm volatile("ldmatrix.sync.aligned.m8n8.x4.shared.b16 {%0,%1,%2,%3}, [%4];"
        : "=r"(r[0]), "=r"(r[1]), "=r"(r[2]), "=r"(r[3]) : "r"(addr));
}
__device__ __forceinline__ void ldsm_x4_t(uint32_t* r, uint32_t addr) {
    asm volatile("ldmatrix.sync.aligned.m8n8.x4.trans.shared.b16 {%0,%1,%2,%3}, [%4];"
        : "=r"(r[0]), "=r"(r[1]), "=r"(r[2]), "=r"(r[3]) : "r"(addr));
}
__device__ __forceinline__ void mma_bf16(float* d, const uint32_t* a,
                                         uint32_t b0, uint32_t b1) {
    asm volatile(
        "mma.sync.aligned.m16n8k16.row.col.f32.bf16.bf16.f32 "
        "{%0,%1,%2,%3}, {%4,%5,%6,%7}, {%8,%9}, {%0,%1,%2,%3};"
        : "+f"(d[0]), "+f"(d[1]), "+f"(d[2]), "+f"(d[3])
        : "r"(a[0]), "r"(a[1]), "r"(a[2]), "r"(a[3]), "r"(b0), "r"(b1));
}
__device__ __forceinline__ void cpasync16(uint32_t dst, const void* src,
                                          uint32_t srcsize) {
    asm volatile("cp.async.cg.shared.global [%0], [%1], 16, %2;"
        :: "r"(dst), "l"(src), "r"(srcsize));
}
__device__ __forceinline__ void cpasync_commit() {
    asm volatile("cp.async.commit_group;" ::: "memory");
}
#define CPASYNC_WAIT1() asm volatile("cp.async.wait_group 1;" ::: "memory")

// ---------------------------------------------------------------------------
// Kernel 1: groupwise-correlation cost volume (unchanged, known-good)
// ---------------------------------------------------------------------------
__global__ void __launch_bounds__(256) vol_kernel(const float* __restrict__ fl,
                                                  const float* __restrict__ fr) {
    __shared__ float sFl[CPG][WW];
    __shared__ float sFr[CPG][WW];
    const int h = blockIdx.x, g = blockIdx.y, b = blockIdx.z;
    const int tid = threadIdx.x;

    const float* flb = fl + ((size_t)b*CIN + g*CPG)*HW + h*WW;
    const float* frb = fr + ((size_t)b*CIN + g*CPG)*HW + h*WW;
    for (int i = tid; i < CPG*WW; i += 256) {
        int c = i / WW, w = i % WW;
        sFl[c][w] = flb[c*HW + w];
        sFr[c][w] = frb[c*HW + w];
    }
    __syncthreads();

    float* dst = g_vol + ((size_t)b*G + g)*DHW + h*WW;
    for (int i = tid; i < DD*WW; i += 256) {
        int d = i / WW, w = i % WW;
        float v = 0.f;
        if (w >= d) {
            float s = 0.f;
            #pragma unroll
            for (int c = 0; c < CPG; c++) s += sFl[c][w] * sFr[c][w-d];
            v = s * (1.0f/CPG);
        }
        dst[d*HW + w] = v;
    }
}

// ---------------------------------------------------------------------------
// Kernel 1b: transpose g_vol -> g_volT_{h,l}: [b][d][h][w][ic] bf16 hi/lo.
// ---------------------------------------------------------------------------
__global__ void __launch_bounds__(256) volT_kernel() {
    __shared__ float sT[32*241];
    const int h = blockIdx.x, d = blockIdx.y, b = blockIdx.z;
    const int tid = threadIdx.x;

    const float* src = g_vol + (size_t)b*G*DHW + (size_t)d*HW + h*WW;
    for (int i = tid; i < 32*240; i += 256) {
        int ic = i / 240, w = i - ic*240;
        sT[ic*241 + w] = src[(size_t)ic*DHW + w];
    }
    __syncthreads();

    const size_t base = (size_t)(((b*DD + d)*HH + h))*WW*32;
    uint16_t* __restrict__ dh = g_volT_h + base;
    uint16_t* __restrict__ dl = g_volT_l + base;
    for (int i = tid; i < 240*32; i += 256) {
        int w = i >> 5, ic = i & 31;
        float x = sT[ic*241 + w];
        __nv_bfloat16 xh = __float2bfloat16_rn(x);
        __nv_bfloat16 xl = __float2bfloat16_rn(x - __bfloat162float(xh));
        dh[i] = __bfloat16_as_ushort(xh);
        dl[i] = __bfloat16_as_ushort(xl);
    }
}

// ---------------------------------------------------------------------------
// Kernel 1c: repack w1 -> g_w1T_{h,l}[k][ic][oc] bf16 hi/lo (tiny, one block)
// ---------------------------------------------------------------------------
__global__ void __launch_bounds__(512) w1T_kernel(const float* __restrict__ w1) {
    const int tid = threadIdx.x;
    for (int i = tid; i < 27*32*32; i += 512) {
        int k = i >> 10, ic = (i >> 5) & 31, oc = i & 31;
        float x = w1[(size_t)oc*864 + ic*27 + k];
        __nv_bfloat16 xh = __float2bfloat16_rn(x);
        __nv_bfloat16 xl = __float2bfloat16_rn(x - __bfloat162float(xh));
        g_w1T_h[i] = __bfloat16_as_ushort(xh);
        g_w1T_l[i] = __bfloat16_as_ushort(xl);
    }
}

// ---------------------------------------------------------------------------
// Kernel 2: Conv3d(32->32,k3,p1)+BN+ReLU via mma.sync bf16, 3-product hi/lo.
// cp.async double-buffered pipeline (byte-identical mainloop to the R8 pass);
// epilogue writes TRANSPOSED fp32 g_vol2T[b][d][h][w][oc] via float2 stores.
// ---------------------------------------------------------------------------
#define ASTRIDE 40
#define AROWS   264
#define STG_A_H 0
#define STG_A_L (AROWS*ASTRIDE*2)            // 21120
#define STG_B   (2*AROWS*ASTRIDE*2)          // 42240
#define STG_SIZE (STG_B + 2*3*32*ASTRIDE*2)  // 57600 per buffer
#define SBN_OFF (2*STG_SIZE)                 // 115200
#define CONV1_SMEM (SBN_OFF + 256)           // 115456

__device__ __forceinline__ void fill_stage(uint32_t sbuf, size_t abase,
                                           int kbase, int tid) {
    #pragma unroll 1
    for (int u = tid; u < 2*AROWS*4; u += 512) {
        const int plane = (u >= AROWS*4);
        const int v = plane ? u - AROWS*4 : u;
        const int r = v >> 2, q = v & 3;
        const int w = r - 1;
        const int ok = (w >= 0 && w < WW);
        const uint16_t* sp = (plane ? g_volT_l : g_volT_h) + abase
                             + (size_t)(ok ? w : 0)*32 + q*8;
        cpasync16(sbuf + (plane ? STG_A_L : STG_A_H) + (r*ASTRIDE + q*8)*2,
                  sp, ok ? 16u : 0u);
    }
    #pragma unroll 1
    for (int u = tid; u < 2*3*32*4; u += 512) {
        const int plane = (u >= 3*32*4);
        const int v = plane ? u - 3*32*4 : u;
        const int kw = v >> 7, rest = v & 127;
        const int ic = rest >> 2, q = rest & 3;
        const uint16_t* sp = (plane ? g_w1T_l : g_w1T_h)
                             + ((kbase + kw)*32 + ic)*32 + q*8;
        cpasync16(sbuf + STG_B + ((plane*3 + kw)*32 + ic)*ASTRIDE*2 + q*16,
                  sp, 16u);
    }
}

__global__ void __launch_bounds__(512)
conv1_mma_kernel(const float* __restrict__ gamma, const float* __restrict__ beta,
                 const float* __restrict__ mean, const float* __restrict__ var) {
    extern __shared__ char smc[];
    const uint32_t sb = smem_to_u32(smc);
    float* sBN = (float*)(smc + SBN_OFF);    // sc[32], sh[32]

    const int tid = threadIdx.x, wid = tid >> 5, t = tid & 31;
    const int h = blockIdx.x, d = blockIdx.y, b = blockIdx.z;
    const int m0 = wid * 16;
    const uint32_t lrow = (uint32_t)(t & 15);
    const uint32_t lcol = (uint32_t)((t & 16) >> 1);   // 0 or 8

    if (tid < 32) {
        float sc = gamma[tid] * rsqrtf(var[tid] + 1e-5f);
        sBN[tid] = sc;
        sBN[32 + tid] = beta[tid] - mean[tid] * sc;
    }

    float acc[4][4];
    #pragma unroll
    for (int n = 0; n < 4; n++)
        #pragma unroll
        for (int j = 0; j < 4; j++) acc[n][j] = 0.f;

    size_t sab[9]; int skb[9]; int nst = 0;
    for (int kd = 0; kd < 3; kd++) {
        const int dd = d + kd - 1;
        if (dd < 0 || dd >= DD) continue;
        for (int kh = 0; kh < 3; kh++) {
            const int hhr = h + kh - 1;
            if (hhr < 0 || hhr >= HH) continue;
            sab[nst] = (size_t)(((b*DD + dd)*HH + hhr))*WW*32;
            skb[nst] = kd*9 + kh*3;
            nst++;
        }
    }

    fill_stage(sb, sab[0], skb[0], tid);
    cpasync_commit();

    for (int s = 0; s < nst; s++) {
        if (s + 1 < nst)
            fill_stage(sb + ((s + 1) & 1)*STG_SIZE, sab[s+1], skb[s+1], tid);
        cpasync_commit();
        CPASYNC_WAIT1();
        __syncthreads();

        const uint32_t ab = sb + (s & 1)*STG_SIZE;
        const uint32_t aH = ab + STG_A_H, aL = ab + STG_A_L, bB = ab + STG_B;
        #pragma unroll
        for (int kw = 0; kw < 3; kw++) {
            #pragma unroll
            for (int ks = 0; ks < 2; ks++) {
                const uint32_t aoff =
                    2*(((uint32_t)(m0 + kw) + lrow)*ASTRIDE + ks*16 + lcol);
                uint32_t Ah[4], Al[4];
                ldsm_x4(Ah, aH + aoff);
                ldsm_x4(Al, aL + aoff);
                #pragma unroll
                for (int np = 0; np < 2; np++) {
                    const uint32_t boff =
                        2*(((uint32_t)kw*32 + ks*16 + lrow)*ASTRIDE + np*16 + lcol);
                    uint32_t Bh[4], Bl[4];
                    ldsm_x4_t(Bh, bB + boff);
                    ldsm_x4_t(Bl, bB + 3*32*ASTRIDE*2 + boff);
                    mma_bf16(acc[np*2    ], Ah, Bh[0], Bh[1]);
                    mma_bf16(acc[np*2 + 1], Ah, Bh[2], Bh[3]);
                    mma_bf16(acc[np*2    ], Ah, Bl[0], Bl[1]);
                    mma_bf16(acc[np*2 + 1], Ah, Bl[2], Bl[3]);
                    mma_bf16(acc[np*2    ], Al, Bh[0], Bh[1]);
                    mma_bf16(acc[np*2 + 1], Al, Bh[2], Bh[3]);
                }
            }
        }
        __syncthreads();
    }

    // ---- epilogue: BN + ReLU, TRANSPOSED float2 stores to g_vol2T ----
    const int gr = t >> 2, qc = (t & 3) * 2;
    float* dstb = g_vol2T + (size_t)(((b*DD + d)*HH + h))*WW*32;
    #pragma unroll
    for (int n = 0; n < 4; n++) {
        #pragma unroll
        for (int half = 0; half < 2; half++) {
            const int w = m0 + gr + half*8;
            if (w < WW) {
                const int oc = n*8 + qc;
                float v0 = fmaf(acc[n][half*2    ], sBN[oc    ], sBN[32 + oc    ]);
                float v1 = fmaf(acc[n][half*2 + 1], sBN[oc + 1], sBN[32 + oc + 1]);
                float2 v2;
                v2.x = v0 > 0.f ? v0 : 0.f;
                v2.y = v1 > 0.f ? v1 : 0.f;
                *(float2*)(dstb + (size_t)w*32 + oc) = v2;
            }
        }
    }
}

// ---------------------------------------------------------------------------
// Kernel 3: Conv3d(32->1, k=3, pad=1) -> logits. Reads transposed g_vol2T.
// SIMPLE synchronous version: single smem buffer, coalesced float4 fills
// (warp covers 512B contiguous), 144B-stride rows -> conflict-free LDS.128.
// 38 KB smem -> no opt-in, ~5 blocks/SM for latency hiding.
// ---------------------------------------------------------------------------
#define C2_STRIDE 36                          // floats per row (144B)
#define C2_ROWS   242                         // r = w+1, w = -1..240
#define C2_BUF    (C2_ROWS*C2_STRIDE*4)       // 34848 B
#define CONV2_SMEM (C2_BUF + 27*32*4)         // 38304 B  (< 48K)

__global__ void __launch_bounds__(256) conv2_kernel(const float* __restrict__ w2) {
    extern __shared__ char smc2[];
    float* sX = (float*)smc2;                  // [242][36]
    float* sW = (float*)(smc2 + C2_BUF);       // sW[k*32+ic] = w2[ic*27+k]

    const int h = blockIdx.x, d = blockIdx.y, b = blockIdx.z;
    const int tid = threadIdx.x;

    for (int i = tid; i < 864; i += 256)
        sW[(i % 27)*32 + (i / 27)] = w2[i];

    size_t sab[9]; int skb[9]; int nst = 0;
    for (int kd = 0; kd < 3; kd++) {
        const int dd = d + kd - 1;
        if (dd < 0 || dd >= DD) continue;
        for (int kh = 0; kh < 3; kh++) {
            const int hhr = h + kh - 1;
            if (hhr < 0 || hhr >= HH) continue;
            sab[nst] = (size_t)(((b*DD + dd)*HH + hhr))*WW*32;
            skb[nst] = kd*9 + kh*3;
            nst++;
        }
    }

    float4 acc = make_float4(0.f, 0.f, 0.f, 0.f);
    for (int s = 0; s < nst; s++) {
        __syncthreads();                       // prev compute done
        const float* src = g_vol2T + sab[s];
        for (int u = tid; u < C2_ROWS*8; u += 256) {
            const int r = u >> 3, q = u & 7;
            const int w = r - 1;
            float4 v = make_float4(0.f, 0.f, 0.f, 0.f);
            if (w >= 0 && w < WW)
                v = *(const float4*)(src + (size_t)w*32 + q*4);
            *(float4*)(sX + r*C2_STRIDE + q*4) = v;
        }
        __syncthreads();

        if (tid < WW) {
            const int kbase = skb[s];
            #pragma unroll
            for (int kw = 0; kw < 3; kw++) {
                const float* xrow = sX + (tid + kw)*C2_STRIDE;
                const float* wrow = sW + (kbase + kw)*32;
                #pragma unroll
                for (int q = 0; q < 8; q++) {
                    float4 xv = *(const float4*)(xrow + q*4);
                    float4 wv = *(const float4*)(wrow + q*4);
                    acc.x = fmaf(xv.x, wv.x, acc.x);
                    acc.y = fmaf(xv.y, wv.y, acc.y);
                    acc.z = fmaf(xv.z, wv.z, acc.z);
                    acc.w = fmaf(xv.w, wv.w, acc.w);
                }
            }
        }
    }

    if (tid < WW)
        g_logits[((size_t)b*DD + d)*HW + h*WW + tid] =
            (acc.x + acc.y) + (acc.z + acc.w);
}

// ---------------------------------------------------------------------------
// Kernel 4: softmax over D + disparity expectation (unchanged)
// ---------------------------------------------------------------------------
__global__ void __launch_bounds__(256) softmax_kernel(float* __restrict__ out) {
    const int h = blockIdx.x, b = blockIdx.y;
    const int w = threadIdx.x;
    if (w >= WW) return;
    const float* p = g_logits + (size_t)b*DHW + h*WW + w;
    float m = -1e30f;
    #pragma unroll 4
    for (int d = 0; d < DD; d++) m = fmaxf(m, p[d*HW]);
    float s = 0.f, e = 0.f;
    #pragma unroll 4
    for (int d = 0; d < DD; d++) {
        float t = __expf(p[d*HW] - m);
        s += t;
        e += t * (float)d;
    }
    out[(size_t)b*HW + h*WW + w] = e / s;
}

// ---------------------------------------------------------------------------
extern "C" void kernel_launch(void* const* d_in, const int* in_sizes, int n_in,
                              void* d_out, int out_size) {
    const float* fl    = (const float*)d_in[0];
    const float* fr    = (const float*)d_in[1];
    const float* w1    = (const float*)d_in[2];
    const float* gamma = (const float*)d_in[3];
    const float* beta  = (const float*)d_in[4];
    const float* mean  = (const float*)d_in[5];
    const float* var   = (const float*)d_in[6];
    const float* w2    = (const float*)d_in[7];
    float* out = (float*)d_out;

    cudaFuncSetAttribute(conv1_mma_kernel,
                         cudaFuncAttributeMaxDynamicSharedMemorySize,
                         (int)CONV1_SMEM);

    vol_kernel      <<<dim3(HH, G,  BB), 256>>>(fl, fr);
    volT_kernel     <<<dim3(HH, DD, BB), 256>>>();
    w1T_kernel      <<<1, 512>>>(w1);
    conv1_mma_kernel<<<dim3(HH, DD, BB), 512, CONV1_SMEM>>>(gamma, beta, mean, var);
    conv2_kernel    <<<dim3(HH, DD, BB), 256, CONV2_SMEM>>>(w2);
    softmax_kernel  <<<dim3(HH, BB), 256>>>(out);
}